// round 4
// baseline (speedup 1.0000x reference)
#include <cuda_runtime.h>
#include <math.h>

#define Bsz 4
#define NG  8192
#define Cdim 256
#define Hh  128
#define Ww  128
#define NT  512
#define EPSLN 1e-5f
#define ATTN_SCALE 0.17677669529663687f

__device__ float g_tf [Bsz*NT*Cdim];
__device__ float g_k  [Bsz*NT*Cdim];
__device__ float g_v  [Bsz*NT*Cdim];
__device__ float g_q  [Bsz*NG*Cdim];   // q-proj -> mha-out -> sampled S
__device__ float g_ctx[Bsz*NG*Cdim];   // attn ctx -> LN output
__device__ float g_vt [(size_t)Bsz*Hh*Ww*Cdim];
__device__ float g_oa [Bsz*NG*96];
__device__ float g_wc [96*Cdim];
__device__ float g_bc [96];

// ---- value (B,C,H,W) -> (B,H,W,C) ----
__global__ __launch_bounds__(256) void k_transpose(const float* __restrict__ val) {
    __shared__ float tile[32][33];
    int tx = threadIdx.x, ty = threadIdx.y;
    int b = blockIdx.z, y = blockIdx.y;
    int c0 = (blockIdx.x >> 2) * 32, x0 = (blockIdx.x & 3) * 32;
#pragma unroll
    for (int i = 0; i < 4; i++)
        tile[ty + i * 8][tx] = val[(((size_t)(b * Cdim + c0 + ty + i * 8) * Hh + y) * Ww) + x0 + tx];
    __syncthreads();
#pragma unroll
    for (int i = 0; i < 4; i++)
        g_vt[(((size_t)(b * Hh + y) * Ww + x0 + ty + i * 8) * Cdim) + c0 + tx] = tile[tx][ty + i * 8];
}

// ---- trajectory projection ----
__global__ __launch_bounds__(256) void k_tf(const float* __restrict__ tp,
                                            const float* __restrict__ tw,
                                            const float* __restrict__ tb) {
    int row = blockIdx.x, c = threadIdx.x;
    g_tf[(size_t)row * Cdim + c] =
        fmaf(tp[row * 2], tw[c * 2], fmaf(tp[row * 2 + 1], tw[c * 2 + 1], tb[c]));
}

// ---- concat offs/attw weights + biases ----
__global__ __launch_bounds__(256) void k_concat(const float* __restrict__ ow,
                                                const float* __restrict__ ob,
                                                const float* __restrict__ aw,
                                                const float* __restrict__ ab) {
    int i = blockIdx.x * 256 + threadIdx.x;
    if (i < 64 * 256)                 g_wc[i] = ow[i];
    else if (i < 96 * 256)            g_wc[i] = aw[i - 64 * 256];
    else if (i < 96 * 256 + 64)       g_bc[i - 96 * 256] = ob[i - 96 * 256];
    else if (i < 96 * 256 + 96)       g_bc[i - 96 * 256] = ab[i - 96 * 256 - 64];
}

// ---- Y[R x N] = X[R x 256] @ W[N x 256]^T + bias ; BM=128 BN=64 BK=16 ----
__global__ __launch_bounds__(256) void gemm_bias(const float* __restrict__ X,
                                                 const float* __restrict__ W,
                                                 const float* __restrict__ bias,
                                                 float* __restrict__ Y, int N) {
    __shared__ __align__(16) float As[16][132];
    __shared__ __align__(16) float Bs[16][68];
    int tid = threadIdx.x;
    int row0 = blockIdx.y * 128, n0 = blockIdx.x * 64;
    int rg = tid >> 4, cg = tid & 15;
    float acc[8][4];
#pragma unroll
    for (int i = 0; i < 8; i++)
#pragma unroll
        for (int j = 0; j < 4; j++) acc[i][j] = 0.f;

    int ar = tid >> 1, akq = (tid & 1) * 8;
    int bn = tid >> 2, bkq = (tid & 3) * 4;
    bool bvalid = (n0 + bn) < N;
    const float* Xp = X + (size_t)(row0 + ar) * 256 + akq;
    const float* Wp = W + (size_t)(n0 + bn) * 256 + bkq;

    for (int kt = 0; kt < 16; kt++) {
        int k0 = kt * 16;
        float4 a0 = *(const float4*)(Xp + k0);
        float4 a1 = *(const float4*)(Xp + k0 + 4);
        float4 b0 = bvalid ? *(const float4*)(Wp + k0) : make_float4(0.f, 0.f, 0.f, 0.f);
        As[akq + 0][ar] = a0.x; As[akq + 1][ar] = a0.y;
        As[akq + 2][ar] = a0.z; As[akq + 3][ar] = a0.w;
        As[akq + 4][ar] = a1.x; As[akq + 5][ar] = a1.y;
        As[akq + 6][ar] = a1.z; As[akq + 7][ar] = a1.w;
        Bs[bkq + 0][bn] = b0.x; Bs[bkq + 1][bn] = b0.y;
        Bs[bkq + 2][bn] = b0.z; Bs[bkq + 3][bn] = b0.w;
        __syncthreads();
#pragma unroll
        for (int kk = 0; kk < 16; kk++) {
            float4 av0 = *(const float4*)&As[kk][rg * 8];
            float4 av1 = *(const float4*)&As[kk][rg * 8 + 4];
            float4 bv  = *(const float4*)&Bs[kk][cg * 4];
            float a[8] = {av0.x, av0.y, av0.z, av0.w, av1.x, av1.y, av1.z, av1.w};
            float bb[4] = {bv.x, bv.y, bv.z, bv.w};
#pragma unroll
            for (int i = 0; i < 8; i++)
#pragma unroll
                for (int j = 0; j < 4; j++) acc[i][j] = fmaf(a[i], bb[j], acc[i][j]);
        }
        __syncthreads();
    }
    int nc = n0 + cg * 4;
    if (nc < N) {
        float4 bb = *(const float4*)(bias + nc);
#pragma unroll
        for (int i = 0; i < 8; i++) {
            float4 o;
            o.x = acc[i][0] + bb.x; o.y = acc[i][1] + bb.y;
            o.z = acc[i][2] + bb.z; o.w = acc[i][3] + bb.w;
            *(float4*)(Y + (size_t)(row0 + rg * 8 + i) * N + nc) = o;
        }
    }
}

// ---- fused per-(b,m) multihead attention, lane-per-query online softmax ----
__global__ __launch_bounds__(256) void k_attn() {
    extern __shared__ __align__(16) float sh[];
    float* Ks = sh;
    float* Vs = sh + 512 * 32;
    int bi = blockIdx.x;
    int qb = bi & 31, m = (bi >> 5) & 7, b = bi >> 8;
    int tid = threadIdx.x;

    for (int t = tid; t < NT; t += 256) {
        const float4* kp = (const float4*)(g_k + ((size_t)(b * NT + t) * Cdim) + m * 32);
        const float4* vp = (const float4*)(g_v + ((size_t)(b * NT + t) * Cdim) + m * 32);
        float4* kd = (float4*)(Ks + t * 32);
        float4* vd = (float4*)(Vs + t * 32);
#pragma unroll
        for (int i = 0; i < 8; i++) { kd[i] = kp[i]; vd[i] = vp[i]; }
    }
    __syncthreads();

    int g = qb * 256 + tid;
    const float4* qp = (const float4*)(g_q + ((size_t)(b * NG + g) * Cdim) + m * 32);
    float q[32];
#pragma unroll
    for (int i = 0; i < 8; i++) {
        float4 t4 = qp[i];
        q[4*i+0] = t4.x * ATTN_SCALE; q[4*i+1] = t4.y * ATTN_SCALE;
        q[4*i+2] = t4.z * ATTN_SCALE; q[4*i+3] = t4.w * ATTN_SCALE;
    }
    float ctx[32];
#pragma unroll
    for (int i = 0; i < 32; i++) ctx[i] = 0.f;
    float mx = -1e30f, sm = 0.f;

#pragma unroll 1
    for (int c0 = 0; c0 < NT; c0 += 16) {
        float s[16];
#pragma unroll
        for (int j = 0; j < 16; j++) {
            const float4* kp4 = (const float4*)(Ks + (c0 + j) * 32);
            float a0 = 0.f, a1 = 0.f, a2 = 0.f, a3 = 0.f;
#pragma unroll
            for (int i = 0; i < 8; i++) {
                float4 kv = kp4[i];
                a0 = fmaf(q[4*i+0], kv.x, a0); a1 = fmaf(q[4*i+1], kv.y, a1);
                a2 = fmaf(q[4*i+2], kv.z, a2); a3 = fmaf(q[4*i+3], kv.w, a3);
            }
            s[j] = (a0 + a1) + (a2 + a3);
        }
        float lm = s[0];
#pragma unroll
        for (int j = 1; j < 16; j++) lm = fmaxf(lm, s[j]);
        float nm = fmaxf(mx, lm);
        float corr = __expf(mx - nm);
        sm *= corr;
#pragma unroll
        for (int i = 0; i < 32; i++) ctx[i] *= corr;
        mx = nm;
#pragma unroll
        for (int j = 0; j < 16; j++) {
            float p = __expf(s[j] - mx);
            sm += p;
            const float4* vp4 = (const float4*)(Vs + (c0 + j) * 32);
#pragma unroll
            for (int i = 0; i < 8; i++) {
                float4 vv = vp4[i];
                ctx[4*i+0] = fmaf(p, vv.x, ctx[4*i+0]); ctx[4*i+1] = fmaf(p, vv.y, ctx[4*i+1]);
                ctx[4*i+2] = fmaf(p, vv.z, ctx[4*i+2]); ctx[4*i+3] = fmaf(p, vv.w, ctx[4*i+3]);
            }
        }
    }
    float inv = 1.f / sm;
    float4* op = (float4*)(g_ctx + ((size_t)(b * NG + g) * Cdim) + m * 32);
#pragma unroll
    for (int i = 0; i < 8; i++) {
        float4 o;
        o.x = ctx[4*i+0] * inv; o.y = ctx[4*i+1] * inv;
        o.z = ctx[4*i+2] * inv; o.w = ctx[4*i+3] * inv;
        op[i] = o;
    }
}

// ---- residual + LayerNorm: g_ctx = LN(g_q + query) ----
__global__ __launch_bounds__(256) void k_ln(const float* __restrict__ q_in,
                                            const float* __restrict__ lng,
                                            const float* __restrict__ lnb) {
    int row = blockIdx.x, t = threadIdx.x;
    size_t base = (size_t)row * Cdim + t;
    float x = g_q[base] + q_in[base];
    __shared__ float red[8];
    int lane = t & 31, w = t >> 5;
    float s = x;
#pragma unroll
    for (int o = 16; o; o >>= 1) s += __shfl_xor_sync(0xffffffffu, s, o);
    if (!lane) red[w] = s;
    __syncthreads();
    float tot = 0.f;
#pragma unroll
    for (int i = 0; i < 8; i++) tot += red[i];
    float mu = tot * (1.f / 256.f);
    float d = x - mu;
    __syncthreads();
    float s2 = d * d;
#pragma unroll
    for (int o = 16; o; o >>= 1) s2 += __shfl_xor_sync(0xffffffffu, s2, o);
    if (!lane) red[w] = s2;
    __syncthreads();
    float tot2 = 0.f;
#pragma unroll
    for (int i = 0; i < 8; i++) tot2 += red[i];
    g_ctx[base] = d * rsqrtf(tot2 * (1.f / 256.f) + EPSLN) * lng[t] + lnb[t];
}

// ---- bilinear corner accumulate ----
__device__ __forceinline__ void corner(const float* __restrict__ vb, int x, int y,
                                       int moff, float w, float4* acc) {
    if (x < 0 || x >= Ww || y < 0 || y >= Hh) return;
    const float4* p = (const float4*)(vb + ((size_t)(y * Ww + x)) * Cdim + moff);
#pragma unroll
    for (int i = 0; i < 8; i++) {
        float4 v = p[i];
        acc[i].x = fmaf(w, v.x, acc[i].x); acc[i].y = fmaf(w, v.y, acc[i].y);
        acc[i].z = fmaf(w, v.z, acc[i].z); acc[i].w = fmaf(w, v.w, acc[i].w);
    }
}

// ---- deformable sampling: thread = (query, m); scrambled store into g_q ----
__global__ __launch_bounds__(128) void k_sample(const float* __restrict__ refp) {
    int bi = blockIdx.x;            // 2048 = B * 8 * 64
    int tid = threadIdx.x;
    int b = bi >> 9;
    int m = (bi >> 6) & 7;
    int gg = (bi & 63) * 128 + tid;
    int gh = gg >> 8, gl = gg & 255;
    size_t qidx = (size_t)b * NG + gg;
    float rx = refp[qidx * 2], ry = refp[qidx * 2 + 1];
    const float* oar = g_oa + qidx * 96;

    float a0 = oar[64 + m * 4], a1 = oar[64 + m * 4 + 1];
    float a2 = oar[64 + m * 4 + 2], a3 = oar[64 + m * 4 + 3];
    float amx = fmaxf(fmaxf(a0, a1), fmaxf(a2, a3));
    float e0 = __expf(a0 - amx), e1 = __expf(a1 - amx);
    float e2 = __expf(a2 - amx), e3 = __expf(a3 - amx);
    float inv = 1.f / (e0 + e1 + e2 + e3);
    float aw[4] = {e0 * inv, e1 * inv, e2 * inv, e3 * inv};

    const float* vb = g_vt + (size_t)b * Hh * Ww * Cdim;
    float4 acc[8];
#pragma unroll
    for (int i = 0; i < 8; i++) acc[i] = make_float4(0.f, 0.f, 0.f, 0.f);

#pragma unroll
    for (int p = 0; p < 4; p++) {
        float gx = (rx + oar[m * 8 + p * 2]) * (float)Ww - 0.5f;
        float gy = (ry + oar[m * 8 + p * 2 + 1]) * (float)Hh - 0.5f;
        float x0f = floorf(gx), y0f = floorf(gy);
        float fx = gx - x0f, fy = gy - y0f;
        int x0 = (int)x0f, y0 = (int)y0f;
        float w = aw[p];
        corner(vb, x0,     y0,     m * 32, (1.f - fx) * (1.f - fy) * w, acc);
        corner(vb, x0 + 1, y0,     m * 32, fx * (1.f - fy) * w, acc);
        corner(vb, x0,     y0 + 1, m * 32, (1.f - fx) * fy * w, acc);
        corner(vb, x0 + 1, y0 + 1, m * 32, fx * fy * w, acc);
    }
    // S[b][ch*256 + m*32 + gh][gl]
    float* S = g_q + (size_t)b * NG * 256 + (size_t)(m * 32 + gh) * 256 + gl;
    const float* af = (const float*)acc;
#pragma unroll
    for (int ch = 0; ch < 32; ch++) S[(size_t)ch * 65536] = af[ch];
}

extern "C" void kernel_launch(void* const* d_in, const int* in_sizes, int n_in,
                              void* d_out, int out_size) {
    const float* query  = (const float*)d_in[0];
    const float* value  = (const float*)d_in[1];
    const float* refp   = (const float*)d_in[2];
    const float* trajp  = (const float*)d_in[3];
    const float* in_w   = (const float*)d_in[4];
    const float* in_b   = (const float*)d_in[5];
    const float* mha_w  = (const float*)d_in[6];
    const float* mha_b  = (const float*)d_in[7];
    const float* ln_g   = (const float*)d_in[8];
    const float* ln_b   = (const float*)d_in[9];
    const float* traj_w = (const float*)d_in[10];
    const float* traj_b = (const float*)d_in[11];
    const float* offs_w = (const float*)d_in[12];
    const float* offs_b = (const float*)d_in[13];
    const float* attw_w = (const float*)d_in[14];
    const float* attw_b = (const float*)d_in[15];
    const float* out_w  = (const float*)d_in[16];
    const float* out_b  = (const float*)d_in[17];
    float* out = (float*)d_out;

    float *p_tf, *p_k, *p_v, *p_q, *p_ctx, *p_oa, *p_wc, *p_bc;
    cudaGetSymbolAddress((void**)&p_tf,  g_tf);
    cudaGetSymbolAddress((void**)&p_k,   g_k);
    cudaGetSymbolAddress((void**)&p_v,   g_v);
    cudaGetSymbolAddress((void**)&p_q,   g_q);
    cudaGetSymbolAddress((void**)&p_ctx, g_ctx);
    cudaGetSymbolAddress((void**)&p_oa,  g_oa);
    cudaGetSymbolAddress((void**)&p_wc,  g_wc);
    cudaGetSymbolAddress((void**)&p_bc,  g_bc);

    cudaFuncSetAttribute(k_attn, cudaFuncAttributeMaxDynamicSharedMemorySize, 131072);

    k_transpose<<<dim3(32, 128, 4), dim3(32, 8)>>>(value);
    k_tf<<<Bsz * NT, 256>>>(trajp, traj_w, traj_b);
    k_concat<<<97, 256>>>(offs_w, offs_b, attw_w, attw_b);

    // q/k/v projections
    gemm_bias<<<dim3(4, 256), 256>>>(query, in_w,             in_b,       p_q, 256);
    gemm_bias<<<dim3(4, 16),  256>>>(p_tf,  in_w + 256 * 256, in_b + 256, p_k, 256);
    gemm_bias<<<dim3(4, 16),  256>>>(p_tf,  in_w + 512 * 256, in_b + 512, p_v, 256);

    k_attn<<<1024, 256, 131072>>>();

    // mha out projection (ctx -> g_q)
    gemm_bias<<<dim3(4, 256), 256>>>(p_ctx, mha_w, mha_b, p_q, 256);

    // residual + LN (g_q + query -> g_ctx)
    k_ln<<<Bsz * NG, 256>>>(query, ln_g, ln_b);

    // offs + attw fused GEMM (g_ctx -> g_oa), N=96
    gemm_bias<<<dim3(2, 256), 256>>>(p_ctx, p_wc, p_bc, p_oa, 96);

    // deformable sampling (writes scrambled S into g_q)
    k_sample<<<2048, 128>>>(refp);

    // final projection
    gemm_bias<<<dim3(4, 256), 256>>>(p_q, out_w, out_b, out, 256);
}